// round 16
// baseline (speedup 1.0000x reference)
#include <cuda_runtime.h>
#include <cuda_bf16.h>
#include <math.h>

// ---------------------------------------------------------------------------
// MambaMIL_2D forward. All GEMMs on HMMA split-bf16 (cp.async pipeline,
// 512-thread CTAs for 32 warps/SM), chunked scan w/ inline carry,
// fused softmax-pool, specialized ConvTranspose.
// ---------------------------------------------------------------------------

#define L 2048
#define DM 512
#define DI 1024
#define DS 16
#define DTR 32
#define NCH 16
#define CHT 128

typedef unsigned long long u64;
typedef unsigned int u32;

// ------------------------------- scratch ----------------------------------
__device__ float g_h   [L * DM];
__device__ float g_hn  [L * DM];
__device__ float g_xz  [L * 2 * DI];
__device__ float g_dbc [L * 64];
__device__ float g_delta[L * DI];
__device__ float g_s   [L];
__device__ float g_pooled[DM];
__device__ float g_part[4 * 1024 * 1024];
__device__ float g_c1[256 * 16];
__device__ float g_c2[128 * 256];
__device__ float g_c3[64 * 1024];
__device__ float g_c4[32 * 4096];
__device__ float g_ap[NCH * DI * DS];
__device__ float g_he[NCH * DI * DS];

// split-bf16 A operands
__device__ __align__(16) __nv_bfloat16 g_xh[L * 1024], g_xl[L * 1024];
__device__ __align__(16) __nv_bfloat16 g_hnh[L * DM], g_hnl[L * DM];
__device__ __align__(16) __nv_bfloat16 g_yh[L * DI], g_yl[L * DI];
__device__ __align__(16) __nv_bfloat16 g_xih[L * DI], g_xil[L * DI];
__device__ __align__(16) __nv_bfloat16 g_dth[L * DTR], g_dtl[L * DTR];

// split-bf16 transposed weights [N,K]
__device__ __align__(16) __nv_bfloat16 g_wfc1h[512 * 1024], g_wfc1l[512 * 1024];
__device__ __align__(16) __nv_bfloat16 g_winh[2 * 2048 * 512], g_winl[2 * 2048 * 512];
__device__ __align__(16) __nv_bfloat16 g_wouth[2 * 512 * 1024], g_woutl[2 * 512 * 1024];
__device__ __align__(16) __nv_bfloat16 g_wa1h[128 * 512], g_wa1l[128 * 512];
__device__ __align__(16) __nv_bfloat16 g_wxwh[2 * 64 * 1024], g_wxwl[2 * 64 * 1024];
__device__ __align__(16) __nv_bfloat16 g_wdth[2 * 1024 * 32], g_wdtl[2 * 1024 * 32];

// ------------------------------ math helpers ------------------------------
__device__ __forceinline__ float geluf(float x) {
    return 0.5f * x * (1.f + erff(x * 0.70710678118654752f));
}
__device__ __forceinline__ float softplusf(float x) {
    return (x > 20.f) ? x : log1pf(__expf(x));
}
__device__ __forceinline__ float siluf(float x) {
    return x / (1.f + __expf(-x));
}
__device__ __forceinline__ float ex2f(float x) {
    float r; asm("ex2.approx.ftz.f32 %0, %1;" : "=f"(r) : "f"(x)); return r;
}
__device__ __forceinline__ void store_split(__nv_bfloat16* hi, __nv_bfloat16* lo,
                                            size_t idx, float v) {
    __nv_bfloat16 h = __float2bfloat16_rn(v);
    hi[idx] = h;
    lo[idx] = __float2bfloat16_rn(v - __bfloat162float(h));
}

// --------------------------- HMMA / async helpers --------------------------
__device__ __forceinline__ u32 smem_u32(const void* p) {
    u32 a;
    asm("{ .reg .u64 t; cvta.to.shared.u64 t, %1; cvt.u32.u64 %0, t; }" : "=r"(a) : "l"(p));
    return a;
}
__device__ __forceinline__ void ldsm4(u32* r, u32 addr) {
    asm volatile("ldmatrix.sync.aligned.m8n8.x4.shared.b16 {%0,%1,%2,%3}, [%4];"
                 : "=r"(r[0]), "=r"(r[1]), "=r"(r[2]), "=r"(r[3]) : "r"(addr));
}
__device__ __forceinline__ void mma_bf16(float* c, const u32* a, const u32* b) {
    asm volatile("mma.sync.aligned.m16n8k16.row.col.f32.bf16.bf16.f32 "
                 "{%0,%1,%2,%3}, {%4,%5,%6,%7}, {%8,%9}, {%0,%1,%2,%3};"
                 : "+f"(c[0]), "+f"(c[1]), "+f"(c[2]), "+f"(c[3])
                 : "r"(a[0]), "r"(a[1]), "r"(a[2]), "r"(a[3]), "r"(b[0]), "r"(b[1]));
}
__device__ __forceinline__ void cpa16(u32 dst, const void* src) {
    asm volatile("cp.async.ca.shared.global [%0], [%1], 16;" :: "r"(dst), "l"(src));
}
#define CP_COMMIT() asm volatile("cp.async.commit_group;" ::: "memory")
#define CP_WAIT1()  asm volatile("cp.async.wait_group 1;" ::: "memory")

// -------- all weight transposes + x split in ONE segmented kernel ----------
__device__ __forceinline__ void wsplit_tile(const float* W, int K, int N,
                                            __nv_bfloat16* hi, __nv_bfloat16* lo,
                                            int lb, int tid)
{
    __shared__ float tile[32][33];
    int gx = K >> 5;
    int bk = (lb % gx) * 32, bn = (lb / gx) * 32;
    int tx = tid & 31, ty = tid >> 5;
#pragma unroll
    for (int i = 0; i < 32; i += 8)
        tile[ty + i][tx] = W[(size_t)(bk + ty + i) * N + bn + tx];
    __syncthreads();
#pragma unroll
    for (int i = 0; i < 32; i += 8)
        store_split(hi, lo, (size_t)(bn + ty + i) * K + bk + tx, tile[tx][ty + i]);
}

__global__ __launch_bounds__(256) void wsplit_all_k(
    const float* __restrict__ W_fc1, const float* __restrict__ in_w,
    const float* __restrict__ out_w, const float* __restrict__ Wa1,
    const float* __restrict__ x_w, const float* __restrict__ dt_w,
    const float* __restrict__ x,
    __nv_bfloat16* wfc1h, __nv_bfloat16* wfc1l,
    __nv_bfloat16* winh, __nv_bfloat16* winl,
    __nv_bfloat16* wouth, __nv_bfloat16* woutl,
    __nv_bfloat16* wa1h, __nv_bfloat16* wa1l,
    __nv_bfloat16* wxwh, __nv_bfloat16* wxwl,
    __nv_bfloat16* wdth, __nv_bfloat16* wdtl,
    __nv_bfloat16* xh, __nv_bfloat16* xl)
{
    int b = blockIdx.x, tid = threadIdx.x;
    if (b < 512) {
        wsplit_tile(W_fc1, 1024, 512, wfc1h, wfc1l, b, tid);
    } else if (b < 1536) {
        wsplit_tile(in_w, 512, 2048, winh, winl, b - 512, tid);
    } else if (b < 2560) {
        wsplit_tile(in_w + (size_t)512 * 2048, 512, 2048,
                    winh + (size_t)2048 * 512, winl + (size_t)2048 * 512, b - 1536, tid);
    } else if (b < 3072) {
        wsplit_tile(out_w, 1024, 512, wouth, woutl, b - 2560, tid);
    } else if (b < 3584) {
        wsplit_tile(out_w + (size_t)1024 * 512, 1024, 512,
                    wouth + (size_t)512 * 1024, woutl + (size_t)512 * 1024, b - 3072, tid);
    } else if (b < 3648) {
        wsplit_tile(Wa1, 512, 128, wa1h, wa1l, b - 3584, tid);
    } else if (b < 3712) {
        wsplit_tile(x_w, 1024, 64, wxwh, wxwl, b - 3648, tid);
    } else if (b < 3776) {
        wsplit_tile(x_w + (size_t)1024 * 64, 1024, 64,
                    wxwh + (size_t)64 * 1024, wxwl + (size_t)64 * 1024, b - 3712, tid);
    } else if (b < 3808) {
        wsplit_tile(dt_w, 32, 1024, wdth, wdtl, b - 3776, tid);
    } else if (b < 3840) {
        wsplit_tile(dt_w + (size_t)32 * 1024, 32, 1024,
                    wdth + (size_t)1024 * 32, wdtl + (size_t)1024 * 32, b - 3808, tid);
    } else {
        int idx = (b - 3840) * 256 + tid;      // x elementwise split
        if (idx < L * 1024) store_split(xh, xl, idx, x[idx]);
    }
}

// ------------------------ HMMA split-bf16 GEMM ------------------------------
// 512 threads, 16 warps (8m x 2n), warp tile 16x32, CTA tile 128x64, BK=32,
// 3-stage cp.async, 2 CTAs/SM (32 warps). Split-K via gridDim.z.
// epi (slices==1 only): 0 none, 3 softplus(v + bias[col])
#define SPAD 40
#define A_STG (128 * SPAD * 2)
#define B_STG (64 * SPAD * 2)
#define STGB (2 * A_STG + 2 * B_STG)
#define HSMEM (3 * STGB)

__global__ void __launch_bounds__(512, 2) hmma_gemm_k(
    int M, int N, int K,
    const __nv_bfloat16* __restrict__ Ahi, const __nv_bfloat16* __restrict__ Alo,
    const __nv_bfloat16* __restrict__ Bhi, const __nv_bfloat16* __restrict__ Blo,
    float* __restrict__ C, int ldc,
    int epi, const float* __restrict__ bias)
{
    extern __shared__ char dsm[];
    int tid = threadIdx.x, lane = tid & 31, wid = tid >> 5;
    int bm = blockIdx.y, bn = blockIdx.x, bz = blockIdx.z;
    int slices = gridDim.z;
    int Ks = K / slices;
    int kbase = bz * Ks;
    int wm = wid & 7, wn = wid >> 3;
    int NC = Ks / 32;

    u32 sb = smem_u32(dsm);

    float acc[4][4];
#pragma unroll
    for (int nt = 0; nt < 4; nt++)
#pragma unroll
        for (int q = 0; q < 4; q++) acc[nt][q] = 0.f;

    // per-stage async load: A 2x16B + B 1x16B per thread
    auto issue = [&](int kc, int stg) {
        u32 base = sb + stg * STGB;
        {
            int r = tid >> 2, kq = tid & 3;     // A: 128 rows x 4 chunks = 512
            size_t goff = (size_t)(bm * 128 + r) * K + kbase + kc * 32 + kq * 8;
            u32 doff = (u32)(r * SPAD + kq * 8) * 2;
            cpa16(base + doff, Ahi + goff);
            cpa16(base + A_STG + doff, Alo + goff);
        }
        {
            int s = tid & 255;
            int r = s >> 2, kq = s & 3;          // B: 64 rows x 4 chunks = 256
            size_t goff = (size_t)(bn * 64 + r) * K + kbase + kc * 32 + kq * 8;
            u32 doff = (u32)(r * SPAD + kq * 8) * 2;
            if (tid < 256) cpa16(base + 2 * A_STG + doff, Bhi + goff);
            else           cpa16(base + 2 * A_STG + B_STG + doff, Blo + goff);
        }
    };

    issue(0, 0); CP_COMMIT();
    if (NC > 1) issue(1, 1);
    CP_COMMIT();

    for (int kc = 0; kc < NC; kc++) {
        CP_WAIT1();
        __syncthreads();
        int stg = kc % 3;
        u32 bAh = sb + stg * STGB;
        u32 bAl = bAh + A_STG;
        u32 bBh = bAh + 2 * A_STG;
        u32 bBl = bBh + B_STG;
#pragma unroll
        for (int ks = 0; ks < 2; ks++) {
            u32 ah[4], al[4];
            {
                int row = wm * 16 + ((lane >> 3) & 1) * 8 + (lane & 7);
                int kcol = ks * 16 + (lane >> 4) * 8;
                u32 off = (u32)(row * SPAD + kcol) * 2;
                ldsm4(ah, bAh + off);
                ldsm4(al, bAl + off);
            }
            u32 bh[4][2], bl[4][2];
#pragma unroll
            for (int p = 0; p < 2; p++) {
                int n = wn * 32 + p * 16 + (lane >> 4) * 8 + (lane & 7);
                int kcol = ks * 16 + ((lane >> 3) & 1) * 8;
                u32 off = (u32)(n * SPAD + kcol) * 2;
                u32 r4[4];
                ldsm4(r4, bBh + off);
                bh[p * 2][0] = r4[0]; bh[p * 2][1] = r4[1];
                bh[p * 2 + 1][0] = r4[2]; bh[p * 2 + 1][1] = r4[3];
                ldsm4(r4, bBl + off);
                bl[p * 2][0] = r4[0]; bl[p * 2][1] = r4[1];
                bl[p * 2 + 1][0] = r4[2]; bl[p * 2 + 1][1] = r4[3];
            }
#pragma unroll
            for (int nt = 0; nt < 4; nt++) {
                mma_bf16(acc[nt], ah, bh[nt]);
                mma_bf16(acc[nt], ah, bl[nt]);
                mma_bf16(acc[nt], al, bh[nt]);
            }
        }
        if (kc + 2 < NC) issue(kc + 2, (kc + 2) % 3);
        CP_COMMIT();
    }

    if (slices == 1) {
        int row0 = bm * 128 + wm * 16 + (lane >> 2);
#pragma unroll
        for (int nt = 0; nt < 4; nt++) {
            int col = bn * 64 + wn * 32 + nt * 8 + (lane & 3) * 2;
#pragma unroll
            for (int q = 0; q < 4; q++) {
                int row = row0 + (q >> 1) * 8;
                int cc = col + (q & 1);
                float v = acc[nt][q];
                if (epi == 3) v = softplusf(v + bias[cc]);
                C[(size_t)row * ldc + cc] = v;
            }
        }
    } else {
        float* Cp = C + (size_t)bz * M * N;
        int row0 = bm * 128 + wm * 16 + (lane >> 2);
#pragma unroll
        for (int nt = 0; nt < 4; nt++) {
            int col = bn * 64 + wn * 32 + nt * 8 + (lane & 3) * 2;
            Cp[(size_t)row0 * N + col]           = acc[nt][0];
            Cp[(size_t)row0 * N + col + 1]       = acc[nt][1];
            Cp[(size_t)(row0 + 8) * N + col]     = acc[nt][2];
            Cp[(size_t)(row0 + 8) * N + col + 1] = acc[nt][3];
        }
    }
}

// ---------------- dbc reduce: sum slices -> dbc fp32 + dt split -------------
__global__ void reduce_dbc_k(const float* __restrict__ part, int slices,
                             float* __restrict__ dbc,
                             __nv_bfloat16* __restrict__ dth,
                             __nv_bfloat16* __restrict__ dtl)
{
    int idx = blockIdx.x * 256 + threadIdx.x;
    if (idx >= L * 64) return;
    float v = 0.f;
    for (int s = 0; s < slices; s++) v += part[(size_t)s * (L * 64) + idx];
    dbc[idx] = v;
    int col = idx & 63;
    if (col < DTR) {
        int row = idx >> 6;
        store_split(dth, dtl, (size_t)row * DTR + col, v);
    }
}

// ------------- fused split-K reduce + epilogue + RMSNorm + split ------------
__global__ __launch_bounds__(512) void reduce_rms_k(
    const float* __restrict__ part, int slices, int epi,
    const float* __restrict__ bias, const float* __restrict__ coords,
    const float* __restrict__ W_pos, const float* __restrict__ b_pos,
    const float* __restrict__ rmsw,
    float* __restrict__ hout,
    __nv_bfloat16* __restrict__ oh, __nv_bfloat16* __restrict__ ol)
{
    int row = blockIdx.x, c = threadIdx.x;
    size_t idx = (size_t)row * DM + c;
    float v = 0.f;
    for (int s = 0; s < slices; s++) v += part[(size_t)s * (L * DM) + idx];
    if (epi == 1) {
        v += bias[c];
        v = geluf(v);
        v += coords[row * 2 + 0] * W_pos[c] + coords[row * 2 + 1] * W_pos[512 + c] + b_pos[c];
    } else {
        v += hout[idx];
    }
    hout[idx] = v;
    float ss = v * v;
#pragma unroll
    for (int off = 16; off > 0; off >>= 1) ss += __shfl_xor_sync(0xffffffffu, ss, off);
    __shared__ float sm[16];
    if ((c & 31) == 0) sm[c >> 5] = ss;
    __syncthreads();
    float tot = 0.f;
#pragma unroll
    for (int i = 0; i < 16; i++) tot += sm[i];
    float r = rsqrtf(tot / (float)DM + 1e-5f);
    store_split(oh, ol, idx, v * r * rmsw[c]);
}

// ------------- fused split-K reduce + residual + LayerNorm + split ----------
__global__ __launch_bounds__(512) void reduce_ln_k(
    const float* __restrict__ part, int slices,
    const float* __restrict__ h, const float* __restrict__ w,
    const float* __restrict__ b,
    float* __restrict__ hn,
    __nv_bfloat16* __restrict__ oh, __nv_bfloat16* __restrict__ ol)
{
    int row = blockIdx.x, c = threadIdx.x;
    size_t idx = (size_t)row * DM + c;
    float v = 0.f;
    for (int s = 0; s < slices; s++) v += part[(size_t)s * (L * DM) + idx];
    v += h[idx];
    float s1 = v, s2 = v * v;
#pragma unroll
    for (int off = 16; off > 0; off >>= 1) {
        s1 += __shfl_xor_sync(0xffffffffu, s1, off);
        s2 += __shfl_xor_sync(0xffffffffu, s2, off);
    }
    __shared__ float a1[16], a2[16];
    if ((c & 31) == 0) { a1[c >> 5] = s1; a2[c >> 5] = s2; }
    __syncthreads();
    s1 = 0.f; s2 = 0.f;
#pragma unroll
    for (int i = 0; i < 16; i++) { s1 += a1[i]; s2 += a2[i]; }
    float mean = s1 / (float)DM;
    float var = s2 / (float)DM - mean * mean;
    float r = rsqrtf(var + 1e-5f);
    float o = (v - mean) * r * w[c] + b[c];
    hn[idx] = o;
    store_split(oh, ol, idx, o);
}

// -------- fused attention reduce + bias + tanh + Wa2 dot -> score -----------
__global__ __launch_bounds__(128) void reduce_score_k(
    const float* __restrict__ part, int slices,
    const float* __restrict__ ba1, const float* __restrict__ Wa2,
    const float* __restrict__ ba2, float* __restrict__ s)
{
    int row = blockIdx.x, c = threadIdx.x;
    size_t idx = (size_t)row * 128 + c;
    float v = 0.f;
    for (int sl = 0; sl < slices; sl++) v += part[(size_t)sl * (L * 128) + idx];
    v = tanhf(v + ba1[c]);
    float acc = v * Wa2[c];
#pragma unroll
    for (int off = 16; off > 0; off >>= 1) acc += __shfl_xor_sync(0xffffffffu, acc, off);
    __shared__ float sm[4];
    if ((c & 31) == 0) sm[c >> 5] = acc;
    __syncthreads();
    if (c == 0) s[row] = sm[0] + sm[1] + sm[2] + sm[3] + ba2[0];
}

// --------------- depthwise conv + silu -> bf16 split only ------------------
__global__ __launch_bounds__(256) void conv_silu_k(const float* __restrict__ xz,
                                                   const float* __restrict__ cw,
                                                   const float* __restrict__ cb,
                                                   __nv_bfloat16* __restrict__ xih,
                                                   __nv_bfloat16* __restrict__ xil)
{
    int idx = blockIdx.x * 256 + threadIdx.x;
    int t = idx >> 10, d = idx & 1023;
    float w0 = cw[d * 4 + 0], w1 = cw[d * 4 + 1], w2 = cw[d * 4 + 2], w3 = cw[d * 4 + 3];
    float acc = cb[d];
    if (t >= 3) acc = fmaf(xz[(size_t)(t - 3) * 2048 + d], w0, acc);
    if (t >= 2) acc = fmaf(xz[(size_t)(t - 2) * 2048 + d], w1, acc);
    if (t >= 1) acc = fmaf(xz[(size_t)(t - 1) * 2048 + d], w2, acc);
    acc = fmaf(xz[(size_t)t * 2048 + d], w3, acc);
    store_split(xih, xil, idx, siluf(acc));
}

// ---------------------- chunked selective scan ------------------------------
// phase 1: float2-packed smem {delta, xi}
__global__ __launch_bounds__(128) void scan_part_k(
    const float* __restrict__ delta,
    const __nv_bfloat16* __restrict__ xih, const __nv_bfloat16* __restrict__ xil,
    const float* __restrict__ dbc, const float* __restrict__ alog,
    float* __restrict__ aprod, float* __restrict__ hend)
{
    __shared__ float2 sdx[64][8];
    __shared__ float sB[64][16];
    int tid = threadIdx.x;
    int c = blockIdx.x;
    int d0 = blockIdx.y * 8;
    int dloc = tid >> 4, n = tid & 15;
    int d = d0 + dloc;
    float AdnL2 = -__expf(alog[d * DS + n]) * 1.4426950408889634f;
    float h = 0.f, ap = 1.f;
    int tbase = c * CHT;

    for (int sub = 0; sub < 2; sub++) {
        int t0 = tbase + sub * 64;
#pragma unroll
        for (int i = 0; i < 4; i++) {
            int e = tid + i * 128; int r = e >> 3, cc = e & 7;
            size_t gi = (size_t)(t0 + r) * DI + d0 + cc;
            float xv = __bfloat162float(xih[gi]) + __bfloat162float(xil[gi]);
            sdx[r][cc] = make_float2(delta[gi], xv);
        }
#pragma unroll
        for (int i = 0; i < 8; i++) {
            int e = tid + i * 128; int r = e >> 4, cc = e & 15;
            sB[r][cc] = dbc[(size_t)(t0 + r) * 64 + 32 + cc];
        }
        __syncthreads();
#pragma unroll 4
        for (int tt = 0; tt < 64; tt++) {
            float2 dx = sdx[tt][dloc];
            float a = ex2f(dx.x * AdnL2);
            h = fmaf(a, h, dx.x * dx.y * sB[tt][n]);
            ap *= a;
        }
        __syncthreads();
    }
    int idx = c * (DI * DS) + d * DS + n;
    aprod[idx] = ap;
    hend[idx] = h;
}

// phase 2+3 fused: inline carry recompute + local scan + output.
__global__ __launch_bounds__(128) void scan_fix_k(
    const float* __restrict__ delta,
    const __nv_bfloat16* __restrict__ xih, const __nv_bfloat16* __restrict__ xil,
    const float* __restrict__ dbc, const float* __restrict__ xz,
    const float* __restrict__ alog, const float* __restrict__ Dp,
    const float* __restrict__ aprod, const float* __restrict__ hend,
    __nv_bfloat16* __restrict__ yh, __nv_bfloat16* __restrict__ yl)
{
    __shared__ float4 sdxz[64][8];
    __shared__ float sBC[64][32];
    __shared__ float sp[64][8][16];
    __shared__ float sDv[8];
    int tid = threadIdx.x;
    int c = blockIdx.x;
    int d0 = blockIdx.y * 8;
    int dloc = tid >> 4, n = tid & 15;
    int d = d0 + dloc;
    float AdnL2 = -__expf(alog[d * DS + n]) * 1.4426950408889634f;
    if (tid < 8) sDv[tid] = Dp[d0 + tid];

    // inline carry: combine chunks 0..c-1 for this (d,n)
    float h = 0.f;
    int snidx = d * DS + n;
    for (int ch = 0; ch < c; ch++) {
        int ii = ch * (DI * DS) + snidx;
        h = fmaf(aprod[ii], h, hend[ii]);
    }
    int tbase = c * CHT;

    for (int sub = 0; sub < 2; sub++) {
        int t0 = tbase + sub * 64;
#pragma unroll
        for (int i = 0; i < 4; i++) {
            int e = tid + i * 128; int r = e >> 3, cc = e & 7;
            size_t gi = (size_t)(t0 + r) * DI + d0 + cc;
            float xv = __bfloat162float(xih[gi]) + __bfloat162float(xil[gi]);
            float zz = xz[(size_t)(t0 + r) * 2048 + DI + d0 + cc];
            sdxz[r][cc] = make_float4(delta[gi], xv, zz, 0.f);
        }
#pragma unroll
        for (int i = 0; i < 16; i++) {
            int e = tid + i * 128; int r = e >> 5, cc = e & 31;
            sBC[r][cc] = dbc[(size_t)(t0 + r) * 64 + 32 + cc];
        }
        __syncthreads();
#pragma unroll 4
        for (int tt = 0; tt < 64; tt++) {
            float2 dx = *(const float2*)&sdxz[tt][dloc];
            float a = ex2f(dx.x * AdnL2);
            h = fmaf(a, h, dx.x * dx.y * sBC[tt][n]);
            sp[tt][dloc][n] = h * sBC[tt][16 + n];
        }
        __syncthreads();
#pragma unroll
        for (int i = 0; i < 4; i++) {
            int e = tid + i * 128; int r = e >> 3, cc = e & 7;
            float s = 0.f;
#pragma unroll
            for (int nn = 0; nn < 16; nn++) s += sp[r][cc][nn];
            float4 dxz = sdxz[r][cc];
            float val = (s + dxz.y * sDv[cc]) * siluf(dxz.z);
            store_split(yh, yl, (size_t)(t0 + r) * DI + d0 + cc, val);
        }
        __syncthreads();
    }
}

// ------------- fused softmax + pooling partial (16 t-slices) ---------------
__global__ __launch_bounds__(512) void pool_soft_k(const float* __restrict__ sc,
                                                   const float* __restrict__ hn,
                                                   float* __restrict__ part)
{
    __shared__ float red[16];
    __shared__ float e[L];
    __shared__ float stat;
    int b = blockIdx.x, tid = threadIdx.x;
    float4 v = *(const float4*)(sc + tid * 4);
    float m = fmaxf(fmaxf(v.x, v.y), fmaxf(v.z, v.w));
#pragma unroll
    for (int off = 16; off > 0; off >>= 1) m = fmaxf(m, __shfl_xor_sync(0xffffffffu, m, off));
    if ((tid & 31) == 0) red[tid >> 5] = m;
    __syncthreads();
    if (tid == 0) {
        float x = red[0];
#pragma unroll
        for (int i = 1; i < 16; i++) x = fmaxf(x, red[i]);
        stat = x;
    }
    __syncthreads();
    float M = stat;
    float e0 = __expf(v.x - M), e1 = __expf(v.y - M);
    float e2 = __expf(v.z - M), e3 = __expf(v.w - M);
    e[tid * 4 + 0] = e0; e[tid * 4 + 1] = e1;
    e[tid * 4 + 2] = e2; e[tid * 4 + 3] = e3;
    float ss = (e0 + e1) + (e2 + e3);
#pragma unroll
    for (int off = 16; off > 0; off >>= 1) ss += __shfl_xor_sync(0xffffffffu, ss, off);
    __syncthreads();
    if ((tid & 31) == 0) red[tid >> 5] = ss;
    __syncthreads();
    if (tid == 0) {
        float x = 0.f;
#pragma unroll
        for (int i = 0; i < 16; i++) x += red[i];
        stat = x;
    }
    __syncthreads();
    float inv = 1.f / stat;
    int t0 = b * 128;
    float acc = 0.f;
#pragma unroll 8
    for (int t = 0; t < 128; t++)
        acc = fmaf(e[t0 + t], hn[(size_t)(t0 + t) * DM + tid], acc);
    part[b * DM + tid] = acc * inv;
}

__global__ __launch_bounds__(512) void pool_red_k(const float* __restrict__ part,
                                                  float* __restrict__ pooled)
{
    int c = threadIdx.x;
    float acc = 0.f;
#pragma unroll
    for (int s = 0; s < 16; s++) acc += part[s * DM + c];
    pooled[c] = acc;
}

// ---------------- ConvTranspose2d specialized kernels ----------------------
__global__ void convt1_k(const float* __restrict__ in, const float* __restrict__ w,
                         const float* __restrict__ b, float* __restrict__ out,
                         int Cin, int Cout)
{
    int gw = (blockIdx.x * 256 + threadIdx.x) >> 5;
    int lane = threadIdx.x & 31;
    if (gw >= Cout * 16) return;
    int co = gw >> 4;
    int tap = gw & 15;
    const float* ip = in + lane;
    const float* wp = w + (size_t)(lane * Cout + co) * 16 + tap;
    float acc = 0.f;
    int iters = Cin >> 5;
    for (int i = 0; i < iters; i++) {
        acc = fmaf(*ip, *wp, acc);
        ip += 32;
        wp += (size_t)32 * Cout * 16;
    }
#pragma unroll
    for (int off = 16; off > 0; off >>= 1) acc += __shfl_xor_sync(0xffffffffu, acc, off);
    if (lane == 0) out[gw] = fmaxf(acc + b[co], 0.f);
}

__global__ void convt2_k(const float* __restrict__ in, const float* __restrict__ w,
                         const float* __restrict__ b, float* __restrict__ out,
                         int Cin, int Cout)
{
    int gw = (blockIdx.x * 256 + threadIdx.x) >> 5;
    int lane = threadIdx.x & 31;
    if (gw >= Cout * 256) return;
    int co = gw >> 8;
    int r = gw & 255;
    int oy = r >> 4, ox = r & 15;
    int ky = oy & 3, iy = oy >> 2;
    int kx = ox & 3, ix = ox >> 2;
    const float* ip = in + (size_t)lane * 16 + iy * 4 + ix;
    const float* wp = w + (size_t)(lane * Cout + co) * 16 + ky * 4 + kx;
    float acc = 0.f;
    int iters = Cin >> 5;
    for (int i = 0; i < iters; i++) {
        acc = fmaf(*ip, *wp, acc);
        ip += 32 * 16;
        wp += (size_t)32 * Cout * 16;
    }
#pragma unroll
    for (int off = 16; off > 0; off >>= 1) acc += __shfl_xor_sync(0xffffffffu, acc, off);
    if (lane == 0) out[gw] = fmaxf(acc + b[co], 0.f);
}

__global__ void convt_s2_k(const float* __restrict__ in, const float* __restrict__ w,
                           const float* __restrict__ b, float* __restrict__ out,
                           int Cin, int Cout, int Hin, int Hout,
                           int do_relu, int total)
{
    int gw = (blockIdx.x * 256 + threadIdx.x) >> 5;
    int lane = threadIdx.x & 31;
    if (gw >= total) return;
    int hw = Hout * Hout;
    int co = gw / hw;
    int r = gw % hw;
    int oy = r / Hout, ox = r % Hout;
    int p = (oy + 1) & 1, q = (ox + 1) & 1;
    int iy0 = (oy + 1 - p) >> 1, ix0 = (ox + 1 - q) >> 1;
    int HH = Hin * Hin;
    int iters = Cin >> 5;
    float acc = 0.f;
#pragma unroll
    for (int j = 0; j < 2; j++) {
        int iy = iy0 - j;
        if (iy < 0 || iy >= Hin) continue;
        int ky = p + 2 * j;
#pragma unroll
        for (int k = 0; k < 2; k++) {
            int ix = ix0 - k;
            if (ix < 0 || ix >= Hin) continue;
            int kx = q + 2 * k;
            const float* ip = in + (size_t)lane * HH + iy * Hin + ix;
            const float* wp = w + (size_t)(lane * Cout + co) * 16 + ky * 4 + kx;
            for (int i = 0; i < iters; i++) {
                acc = fmaf(*ip, *wp, acc);
                ip += 32 * HH;
                wp += (size_t)32 * Cout * 16;
            }
        }
    }
#pragma unroll
    for (int off = 16; off > 0; off >>= 1) acc += __shfl_xor_sync(0xffffffffu, acc, off);
    if (lane == 0) {
        float v = acc + b[co];
        out[gw] = do_relu ? fmaxf(v, 0.f) : v;
    }
}

// ------------------------------- launcher ----------------------------------
extern "C" void kernel_launch(void* const* d_in, const int* in_sizes, int n_in,
                              void* d_out, int out_size)
{
    const float* x       = (const float*)d_in[0];
    const float* coords  = (const float*)d_in[1];
    const float* W_fc1   = (const float*)d_in[2];
    const float* b_fc1   = (const float*)d_in[3];
    const float* W_pos   = (const float*)d_in[4];
    const float* b_pos   = (const float*)d_in[5];
    const float* in_w    = (const float*)d_in[6];
    const float* conv_w  = (const float*)d_in[7];
    const float* conv_b  = (const float*)d_in[8];
    const float* x_w     = (const float*)d_in[9];
    const float* dt_w    = (const float*)d_in[10];
    const float* dt_b    = (const float*)d_in[11];
    const float* A_log   = (const float*)d_in[12];
    const float* Dp      = (const float*)d_in[13];
    const float* out_w   = (const float*)d_in[14];
    const float* rms_w   = (const float*)d_in[15];
    const float* ln_w    = (const float*)d_in[16];
    const float* ln_b    = (const float*)d_in[17];
    const float* Wa1     = (const float*)d_in[18];
    const float* ba1     = (const float*)d_in[19];
    const float* Wa2     = (const float*)d_in[20];
    const float* ba2     = (const float*)d_in[21];
    const float* ct1_w   = (const float*)d_in[22];
    const float* ct1_b   = (const float*)d_in[23];
    const float* ct2_w   = (const float*)d_in[24];
    const float* ct2_b   = (const float*)d_in[25];
    const float* ct3_w   = (const float*)d_in[26];
    const float* ct3_b   = (const float*)d_in[27];
    const float* ct4_w   = (const float*)d_in[28];
    const float* ct4_b   = (const float*)d_in[29];
    const float* ct5_w   = (const float*)d_in[30];
    const float* ct5_b   = (const float*)d_in[31];

    float *h, *hn, *xz, *dbc, *delta, *sc, *pooled, *part;
    float *c1, *c2, *c3, *c4, *ap, *he;
    __nv_bfloat16 *xh, *xl, *hnh, *hnl, *yh, *yl, *xih, *xil, *dth, *dtl;
    __nv_bfloat16 *wfc1h, *wfc1l, *winh, *winl, *wouth, *woutl, *wa1h, *wa1l;
    __nv_bfloat16 *wxwh, *wxwl, *wdth, *wdtl;
    cudaGetSymbolAddress((void**)&h, g_h);
    cudaGetSymbolAddress((void**)&hn, g_hn);
    cudaGetSymbolAddress((void**)&xz, g_xz);
    cudaGetSymbolAddress((void**)&dbc, g_dbc);
    cudaGetSymbolAddress((void**)&delta, g_delta);
    cudaGetSymbolAddress((void**)&sc, g_s);
    cudaGetSymbolAddress((void**)&pooled, g_pooled);
    cudaGetSymbolAddress((void**)&part, g_part);
    cudaGetSymbolAddress((void**)&c1, g_c1);
    cudaGetSymbolAddress((void**)&c2, g_c2);
    cudaGetSymbolAddress((void**)&c3, g_c3);
    cudaGetSymbolAddress((void**)&c4, g_c4);
    cudaGetSymbolAddress((void**)&ap, g_ap);
    cudaGetSymbolAddress((void**)&he, g_he);
    cudaGetSymbolAddress((void**)&xh, g_xh);
    cudaGetSymbolAddress((void**)&xl, g_xl);
    cudaGetSymbolAddress((void**)&hnh, g_hnh);
    cudaGetSymbolAddress((void**)&hnl, g_hnl);
    cudaGetSymbolAddress((void**)&yh, g_yh);
    cudaGetSymbolAddress((void**)&yl, g_yl);
    cudaGetSymbolAddress((void**)&xih, g_xih);
    cudaGetSymbolAddress((void**)&xil, g_xil);
    cudaGetSymbolAddress((void**)&dth, g_dth);
    cudaGetSymbolAddress((void**)&dtl, g_dtl);
    cudaGetSymbolAddress((void**)&wfc1h, g_wfc1h);
    cudaGetSymbolAddress((void**)&wfc1l, g_wfc1l);
    cudaGetSymbolAddress((void**)&winh, g_winh);
    cudaGetSymbolAddress((void**)&winl, g_winl);
    cudaGetSymbolAddress((void**)&wouth, g_wouth);
    cudaGetSymbolAddress((void**)&woutl, g_woutl);
    cudaGetSymbolAddress((void**)&wa1h, g_wa1h);
    cudaGetSymbolAddress((void**)&wa1l, g_wa1l);
    cudaGetSymbolAddress((void**)&wxwh, g_wxwh);
    cudaGetSymbolAddress((void**)&wxwl, g_wxwl);
    cudaGetSymbolAddress((void**)&wdth, g_wdth);
    cudaGetSymbolAddress((void**)&wdtl, g_wdtl);

    cudaFuncSetAttribute(hmma_gemm_k, cudaFuncAttributeMaxDynamicSharedMemorySize, HSMEM);

    // prep (weights + x split in one kernel)
    wsplit_all_k<<<3840 + (L * 1024) / 256, 256>>>(
        W_fc1, in_w, out_w, Wa1, x_w, dt_w, x,
        wfc1h, wfc1l, winh, winl, wouth, woutl,
        wa1h, wa1l, wxwh, wxwl, wdth, wdtl, xh, xl);
    {
        dim3 g(8, 16, 2);
        hmma_gemm_k<<<g, 512, HSMEM>>>(L, DM, 1024, xh, xl, wfc1h, wfc1l, part, DM,
                                       0, nullptr);
        reduce_rms_k<<<L, 512>>>(part, 2, 1, b_fc1, coords, W_pos, b_pos,
                                 rms_w, h, hnh, hnl);
    }

    // ---- mamba layers ----
    for (int l = 0; l < 2; l++) {
        const float* cw  = conv_w + (size_t)l * DI * 4;
        const float* cb  = conv_b + (size_t)l * DI;
        const float* dtb = dt_b  + (size_t)l * DI;
        const float* al  = A_log + (size_t)l * DI * DS;
        const float* Dl  = Dp    + (size_t)l * DI;

        { // xz = hn @ in_w
            dim3 g(32, 16, 1);
            hmma_gemm_k<<<g, 512, HSMEM>>>(L, 2 * DI, DM, hnh, hnl,
                                           winh + (size_t)l * 2048 * 512,
                                           winl + (size_t)l * 2048 * 512,
                                           xz, 2 * DI, 0, nullptr);
        }

        conv_silu_k<<<(L * DI) / 256, 256>>>(xz, cw, cb, xih, xil);

        { // dbc = xi @ xw via HMMA (split-K 4) + reduce/split
            dim3 g(1, 16, 4);
            hmma_gemm_k<<<g, 512, HSMEM>>>(L, 64, DI, xih, xil,
                                           wxwh + (size_t)l * 64 * 1024,
                                           wxwl + (size_t)l * 64 * 1024,
                                           part, 64, 0, nullptr);
            reduce_dbc_k<<<(L * 64 + 255) / 256, 256>>>(part, 4, dbc, dth, dtl);
        }

        { // delta = softplus(dt @ dtw + dtb) via HMMA (K=32, NC=1)
            dim3 g(16, 16, 1);
            hmma_gemm_k<<<g, 512, HSMEM>>>(L, DI, DTR, dth, dtl,
                                           wdth + (size_t)l * 1024 * 32,
                                           wdtl + (size_t)l * 1024 * 32,
                                           delta, DI, 3, dtb);
        }

        // chunked parallel scan (carry fused into fix)
        scan_part_k<<<dim3(NCH, DI / 8), 128>>>(delta, xih, xil, dbc, al, ap, he);
        scan_fix_k<<<dim3(NCH, DI / 8), 128>>>(delta, xih, xil, dbc, xz, al, Dl,
                                               ap, he, yh, yl);

        { // h += y @ out_w (split-K 2) + fused norm
            dim3 g(8, 16, 2);
            hmma_gemm_k<<<g, 512, HSMEM>>>(L, DM, DI, yh, yl,
                                           wouth + (size_t)l * 512 * 1024,
                                           woutl + (size_t)l * 512 * 1024,
                                           part, DM, 0, nullptr);
            if (l == 0) {
                reduce_rms_k<<<L, 512>>>(part, 2, 2, nullptr, nullptr, nullptr,
                                         nullptr, rms_w + DM, h, hnh, hnl);
            } else {
                reduce_ln_k<<<L, 512>>>(part, 2, h, ln_w, ln_b, hn, hnh, hnl);
            }
        }
    }

    // ---- attention: fused reduce+tanh+score, fused softmax+pool ----
    {
        dim3 g(2, 16, 4);
        hmma_gemm_k<<<g, 512, HSMEM>>>(L, 128, DM, hnh, hnl, wa1h, wa1l, part, 128,
                                       0, nullptr);
        reduce_score_k<<<L, 128>>>(part, 4, ba1, Wa2, ba2, sc);
    }
    pool_soft_k<<<16, 512>>>(sc, hn, part);
    pool_red_k<<<1, 512>>>(part, pooled);

    // ---- ConvTranspose2d stack (specialized) ----
    convt1_k<<<(4096 * 32 + 255) / 256, 256>>>(pooled, ct1_w, ct1_b, c1, 512, 256);
    convt2_k<<<(32768 * 32 + 255) / 256, 256>>>(c1, ct2_w, ct2_b, c2, 256, 128);
    convt_s2_k<<<(65536 * 32 + 255) / 256, 256>>>(c2, ct3_w, ct3_b, c3,
                                                  128, 64, 16, 32, 1, 65536);
    convt_s2_k<<<(131072 * 32 + 255) / 256, 256>>>(c3, ct4_w, ct4_b, c4,
                                                   64, 32, 32, 64, 1, 131072);
    convt_s2_k<<<(180224 * 32 + 255) / 256, 256>>>(c4, ct5_w, ct5_b, (float*)d_out,
                                                   32, 11, 64, 128, 0, 180224);
}

// round 17
// speedup vs baseline: 1.0275x; 1.0275x over previous
#include <cuda_runtime.h>
#include <cuda_bf16.h>
#include <math.h>

// ---------------------------------------------------------------------------
// MambaMIL_2D forward. All GEMMs on HMMA split-bf16 (cp.async.cg pipeline),
// chunked scan w/ inline carry, fused softmax-pool, specialized ConvTranspose.
// ---------------------------------------------------------------------------

#define L 2048
#define DM 512
#define DI 1024
#define DS 16
#define DTR 32
#define NCH 16
#define CHT 128

typedef unsigned long long u64;
typedef unsigned int u32;

// ------------------------------- scratch ----------------------------------
__device__ float g_h   [L * DM];
__device__ float g_hn  [L * DM];
__device__ float g_xz  [L * 2 * DI];
__device__ float g_dbc [L * 64];
__device__ float g_delta[L * DI];
__device__ float g_s   [L];
__device__ float g_pooled[DM];
__device__ float g_part[4 * 1024 * 1024];
__device__ float g_c1[256 * 16];
__device__ float g_c2[128 * 256];
__device__ float g_c3[64 * 1024];
__device__ float g_c4[32 * 4096];
__device__ float g_ap[NCH * DI * DS];
__device__ float g_he[NCH * DI * DS];

// split-bf16 A operands
__device__ __align__(16) __nv_bfloat16 g_xh[L * 1024], g_xl[L * 1024];
__device__ __align__(16) __nv_bfloat16 g_hnh[L * DM], g_hnl[L * DM];
__device__ __align__(16) __nv_bfloat16 g_yh[L * DI], g_yl[L * DI];
__device__ __align__(16) __nv_bfloat16 g_xih[L * DI], g_xil[L * DI];
__device__ __align__(16) __nv_bfloat16 g_dth[L * DTR], g_dtl[L * DTR];

// split-bf16 transposed weights [N,K]
__device__ __align__(16) __nv_bfloat16 g_wfc1h[512 * 1024], g_wfc1l[512 * 1024];
__device__ __align__(16) __nv_bfloat16 g_winh[2 * 2048 * 512], g_winl[2 * 2048 * 512];
__device__ __align__(16) __nv_bfloat16 g_wouth[2 * 512 * 1024], g_woutl[2 * 512 * 1024];
__device__ __align__(16) __nv_bfloat16 g_wa1h[128 * 512], g_wa1l[128 * 512];
__device__ __align__(16) __nv_bfloat16 g_wxwh[2 * 64 * 1024], g_wxwl[2 * 64 * 1024];
__device__ __align__(16) __nv_bfloat16 g_wdth[2 * 1024 * 32], g_wdtl[2 * 1024 * 32];

// ------------------------------ math helpers ------------------------------
__device__ __forceinline__ float geluf(float x) {
    return 0.5f * x * (1.f + erff(x * 0.70710678118654752f));
}
__device__ __forceinline__ float softplusf(float x) {
    return (x > 20.f) ? x : log1pf(__expf(x));
}
__device__ __forceinline__ float siluf(float x) {
    return x / (1.f + __expf(-x));
}
__device__ __forceinline__ float ex2f(float x) {
    float r; asm("ex2.approx.ftz.f32 %0, %1;" : "=f"(r) : "f"(x)); return r;
}
__device__ __forceinline__ void store_split(__nv_bfloat16* hi, __nv_bfloat16* lo,
                                            size_t idx, float v) {
    __nv_bfloat16 h = __float2bfloat16_rn(v);
    hi[idx] = h;
    lo[idx] = __float2bfloat16_rn(v - __bfloat162float(h));
}

// --------------------------- HMMA / async helpers --------------------------
__device__ __forceinline__ u32 smem_u32(const void* p) {
    u32 a;
    asm("{ .reg .u64 t; cvta.to.shared.u64 t, %1; cvt.u32.u64 %0, t; }" : "=r"(a) : "l"(p));
    return a;
}
__device__ __forceinline__ void ldsm4(u32* r, u32 addr) {
    asm volatile("ldmatrix.sync.aligned.m8n8.x4.shared.b16 {%0,%1,%2,%3}, [%4];"
                 : "=r"(r[0]), "=r"(r[1]), "=r"(r[2]), "=r"(r[3]) : "r"(addr));
}
__device__ __forceinline__ void mma_bf16(float* c, const u32* a, const u32* b) {
    asm volatile("mma.sync.aligned.m16n8k16.row.col.f32.bf16.bf16.f32 "
                 "{%0,%1,%2,%3}, {%4,%5,%6,%7}, {%8,%9}, {%0,%1,%2,%3};"
                 : "+f"(c[0]), "+f"(c[1]), "+f"(c[2]), "+f"(c[3])
                 : "r"(a[0]), "r"(a[1]), "r"(a[2]), "r"(a[3]), "r"(b[0]), "r"(b[1]));
}
__device__ __forceinline__ void cpa16(u32 dst, const void* src) {
    asm volatile("cp.async.cg.shared.global [%0], [%1], 16;" :: "r"(dst), "l"(src));
}
#define CP_COMMIT() asm volatile("cp.async.commit_group;" ::: "memory")
#define CP_WAIT1()  asm volatile("cp.async.wait_group 1;" ::: "memory")

// -------- all weight transposes + x split in ONE segmented kernel ----------
__device__ __forceinline__ void wsplit_tile(const float* W, int K, int N,
                                            __nv_bfloat16* hi, __nv_bfloat16* lo,
                                            int lb, int tid)
{
    __shared__ float tile[32][33];
    int gx = K >> 5;
    int bk = (lb % gx) * 32, bn = (lb / gx) * 32;
    int tx = tid & 31, ty = tid >> 5;
#pragma unroll
    for (int i = 0; i < 32; i += 8)
        tile[ty + i][tx] = W[(size_t)(bk + ty + i) * N + bn + tx];
    __syncthreads();
#pragma unroll
    for (int i = 0; i < 32; i += 8)
        store_split(hi, lo, (size_t)(bn + ty + i) * K + bk + tx, tile[tx][ty + i]);
}

__global__ __launch_bounds__(256) void wsplit_all_k(
    const float* __restrict__ W_fc1, const float* __restrict__ in_w,
    const float* __restrict__ out_w, const float* __restrict__ Wa1,
    const float* __restrict__ x_w, const float* __restrict__ dt_w,
    const float* __restrict__ x,
    __nv_bfloat16* wfc1h, __nv_bfloat16* wfc1l,
    __nv_bfloat16* winh, __nv_bfloat16* winl,
    __nv_bfloat16* wouth, __nv_bfloat16* woutl,
    __nv_bfloat16* wa1h, __nv_bfloat16* wa1l,
    __nv_bfloat16* wxwh, __nv_bfloat16* wxwl,
    __nv_bfloat16* wdth, __nv_bfloat16* wdtl,
    __nv_bfloat16* xh, __nv_bfloat16* xl)
{
    int b = blockIdx.x, tid = threadIdx.x;
    if (b < 512) {
        wsplit_tile(W_fc1, 1024, 512, wfc1h, wfc1l, b, tid);
    } else if (b < 1536) {
        wsplit_tile(in_w, 512, 2048, winh, winl, b - 512, tid);
    } else if (b < 2560) {
        wsplit_tile(in_w + (size_t)512 * 2048, 512, 2048,
                    winh + (size_t)2048 * 512, winl + (size_t)2048 * 512, b - 1536, tid);
    } else if (b < 3072) {
        wsplit_tile(out_w, 1024, 512, wouth, woutl, b - 2560, tid);
    } else if (b < 3584) {
        wsplit_tile(out_w + (size_t)1024 * 512, 1024, 512,
                    wouth + (size_t)512 * 1024, woutl + (size_t)512 * 1024, b - 3072, tid);
    } else if (b < 3648) {
        wsplit_tile(Wa1, 512, 128, wa1h, wa1l, b - 3584, tid);
    } else if (b < 3712) {
        wsplit_tile(x_w, 1024, 64, wxwh, wxwl, b - 3648, tid);
    } else if (b < 3776) {
        wsplit_tile(x_w + (size_t)1024 * 64, 1024, 64,
                    wxwh + (size_t)64 * 1024, wxwl + (size_t)64 * 1024, b - 3712, tid);
    } else if (b < 3808) {
        wsplit_tile(dt_w, 32, 1024, wdth, wdtl, b - 3776, tid);
    } else if (b < 3840) {
        wsplit_tile(dt_w + (size_t)32 * 1024, 32, 1024,
                    wdth + (size_t)1024 * 32, wdtl + (size_t)1024 * 32, b - 3808, tid);
    } else {
        int idx = (b - 3840) * 256 + tid;      // x elementwise split
        if (idx < L * 1024) store_split(xh, xl, idx, x[idx]);
    }
}

// ------------------------ HMMA split-bf16 GEMM ------------------------------
// 256 threads, 8 warps (4m x 2n), warp tile 32x32, CTA tile 128x64, BK=32,
// 3-stage cp.async.cg, 2 CTAs/SM. Split-K via gridDim.z.
// epi (slices==1 only): 0 none, 3 softplus(v + bias[col])
#define SPAD 40
#define A_STG (128 * SPAD * 2)
#define B_STG (64 * SPAD * 2)
#define STGB (2 * A_STG + 2 * B_STG)
#define HSMEM (3 * STGB)

__global__ void __launch_bounds__(256, 2) hmma_gemm_k(
    int M, int N, int K,
    const __nv_bfloat16* __restrict__ Ahi, const __nv_bfloat16* __restrict__ Alo,
    const __nv_bfloat16* __restrict__ Bhi, const __nv_bfloat16* __restrict__ Blo,
    float* __restrict__ C, int ldc,
    int epi, const float* __restrict__ bias)
{
    extern __shared__ char dsm[];
    int tid = threadIdx.x, lane = tid & 31, wid = tid >> 5;
    int bm = blockIdx.y, bn = blockIdx.x, bz = blockIdx.z;
    int slices = gridDim.z;
    int Ks = K / slices;
    int kbase = bz * Ks;
    int wm = wid & 3, wn = wid >> 2;
    int NC = Ks / 32;

    u32 sb = smem_u32(dsm);

    float acc[2][4][4];
#pragma unroll
    for (int mt = 0; mt < 2; mt++)
#pragma unroll
        for (int nt = 0; nt < 4; nt++)
#pragma unroll
            for (int q = 0; q < 4; q++) acc[mt][nt][q] = 0.f;

    auto issue = [&](int kc, int stg) {
        u32 base = sb + stg * STGB;
#pragma unroll
        for (int i = 0; i < 2; i++) {
            int s = tid + i * 256;
            int r = s >> 2, kq = s & 3;
            size_t goff = (size_t)(bm * 128 + r) * K + kbase + kc * 32 + kq * 8;
            u32 doff = (u32)(r * SPAD + kq * 8) * 2;
            cpa16(base + doff, Ahi + goff);
            cpa16(base + A_STG + doff, Alo + goff);
        }
        {
            int r = tid >> 2, kq = tid & 3;
            size_t goff = (size_t)(bn * 64 + r) * K + kbase + kc * 32 + kq * 8;
            u32 doff = (u32)(r * SPAD + kq * 8) * 2;
            cpa16(base + 2 * A_STG + doff, Bhi + goff);
            cpa16(base + 2 * A_STG + B_STG + doff, Blo + goff);
        }
    };

    issue(0, 0); CP_COMMIT();
    if (NC > 1) issue(1, 1);
    CP_COMMIT();

    for (int kc = 0; kc < NC; kc++) {
        CP_WAIT1();
        __syncthreads();
        int stg = kc % 3;
        u32 bAh = sb + stg * STGB;
        u32 bAl = bAh + A_STG;
        u32 bBh = bAh + 2 * A_STG;
        u32 bBl = bBh + B_STG;
#pragma unroll
        for (int ks = 0; ks < 2; ks++) {
            u32 ah[2][4], al[2][4];
#pragma unroll
            for (int mt = 0; mt < 2; mt++) {
                int row = wm * 32 + mt * 16 + ((lane >> 3) & 1) * 8 + (lane & 7);
                int kcol = ks * 16 + (lane >> 4) * 8;
                u32 off = (u32)(row * SPAD + kcol) * 2;
                ldsm4(ah[mt], bAh + off);
                ldsm4(al[mt], bAl + off);
            }
            u32 bh[4][2], bl[4][2];
#pragma unroll
            for (int p = 0; p < 2; p++) {
                int n = wn * 32 + p * 16 + (lane >> 4) * 8 + (lane & 7);
                int kcol = ks * 16 + ((lane >> 3) & 1) * 8;
                u32 off = (u32)(n * SPAD + kcol) * 2;
                u32 r4[4];
                ldsm4(r4, bBh + off);
                bh[p * 2][0] = r4[0]; bh[p * 2][1] = r4[1];
                bh[p * 2 + 1][0] = r4[2]; bh[p * 2 + 1][1] = r4[3];
                ldsm4(r4, bBl + off);
                bl[p * 2][0] = r4[0]; bl[p * 2][1] = r4[1];
                bl[p * 2 + 1][0] = r4[2]; bl[p * 2 + 1][1] = r4[3];
            }
#pragma unroll
            for (int mt = 0; mt < 2; mt++)
#pragma unroll
                for (int nt = 0; nt < 4; nt++) {
                    mma_bf16(acc[mt][nt], ah[mt], bh[nt]);
                    mma_bf16(acc[mt][nt], ah[mt], bl[nt]);
                    mma_bf16(acc[mt][nt], al[mt], bh[nt]);
                }
        }
        if (kc + 2 < NC) issue(kc + 2, (kc + 2) % 3);
        CP_COMMIT();
    }

    if (slices == 1) {
#pragma unroll
        for (int mt = 0; mt < 2; mt++) {
            int row0 = bm * 128 + wm * 32 + mt * 16 + (lane >> 2);
#pragma unroll
            for (int nt = 0; nt < 4; nt++) {
                int col = bn * 64 + wn * 32 + nt * 8 + (lane & 3) * 2;
#pragma unroll
                for (int q = 0; q < 4; q++) {
                    int row = row0 + (q >> 1) * 8;
                    int cc = col + (q & 1);
                    float v = acc[mt][nt][q];
                    if (epi == 3) v = softplusf(v + bias[cc]);
                    C[(size_t)row * ldc + cc] = v;
                }
            }
        }
    } else {
        float* Cp = C + (size_t)bz * M * N;
#pragma unroll
        for (int mt = 0; mt < 2; mt++) {
            int row0 = bm * 128 + wm * 32 + mt * 16 + (lane >> 2);
#pragma unroll
            for (int nt = 0; nt < 4; nt++) {
                int col = bn * 64 + wn * 32 + nt * 8 + (lane & 3) * 2;
                Cp[(size_t)row0 * N + col]           = acc[mt][nt][0];
                Cp[(size_t)row0 * N + col + 1]       = acc[mt][nt][1];
                Cp[(size_t)(row0 + 8) * N + col]     = acc[mt][nt][2];
                Cp[(size_t)(row0 + 8) * N + col + 1] = acc[mt][nt][3];
            }
        }
    }
}

// ---------------- dbc reduce: sum slices -> dbc fp32 + dt split -------------
__global__ void reduce_dbc_k(const float* __restrict__ part, int slices,
                             float* __restrict__ dbc,
                             __nv_bfloat16* __restrict__ dth,
                             __nv_bfloat16* __restrict__ dtl)
{
    int idx = blockIdx.x * 256 + threadIdx.x;
    if (idx >= L * 64) return;
    float v = 0.f;
    for (int s = 0; s < slices; s++) v += part[(size_t)s * (L * 64) + idx];
    dbc[idx] = v;
    int col = idx & 63;
    if (col < DTR) {
        int row = idx >> 6;
        store_split(dth, dtl, (size_t)row * DTR + col, v);
    }
}

// ------------- fused split-K reduce + epilogue + RMSNorm + split ------------
__global__ __launch_bounds__(512) void reduce_rms_k(
    const float* __restrict__ part, int slices, int epi,
    const float* __restrict__ bias, const float* __restrict__ coords,
    const float* __restrict__ W_pos, const float* __restrict__ b_pos,
    const float* __restrict__ rmsw,
    float* __restrict__ hout,
    __nv_bfloat16* __restrict__ oh, __nv_bfloat16* __restrict__ ol)
{
    int row = blockIdx.x, c = threadIdx.x;
    size_t idx = (size_t)row * DM + c;
    float v = 0.f;
    for (int s = 0; s < slices; s++) v += part[(size_t)s * (L * DM) + idx];
    if (epi == 1) {
        v += bias[c];
        v = geluf(v);
        v += coords[row * 2 + 0] * W_pos[c] + coords[row * 2 + 1] * W_pos[512 + c] + b_pos[c];
    } else {
        v += hout[idx];
    }
    hout[idx] = v;
    float ss = v * v;
#pragma unroll
    for (int off = 16; off > 0; off >>= 1) ss += __shfl_xor_sync(0xffffffffu, ss, off);
    __shared__ float sm[16];
    if ((c & 31) == 0) sm[c >> 5] = ss;
    __syncthreads();
    float tot = 0.f;
#pragma unroll
    for (int i = 0; i < 16; i++) tot += sm[i];
    float r = rsqrtf(tot / (float)DM + 1e-5f);
    store_split(oh, ol, idx, v * r * rmsw[c]);
}

// ------------- fused split-K reduce + residual + LayerNorm + split ----------
__global__ __launch_bounds__(512) void reduce_ln_k(
    const float* __restrict__ part, int slices,
    const float* __restrict__ h, const float* __restrict__ w,
    const float* __restrict__ b,
    float* __restrict__ hn,
    __nv_bfloat16* __restrict__ oh, __nv_bfloat16* __restrict__ ol)
{
    int row = blockIdx.x, c = threadIdx.x;
    size_t idx = (size_t)row * DM + c;
    float v = 0.f;
    for (int s = 0; s < slices; s++) v += part[(size_t)s * (L * DM) + idx];
    v += h[idx];
    float s1 = v, s2 = v * v;
#pragma unroll
    for (int off = 16; off > 0; off >>= 1) {
        s1 += __shfl_xor_sync(0xffffffffu, s1, off);
        s2 += __shfl_xor_sync(0xffffffffu, s2, off);
    }
    __shared__ float a1[16], a2[16];
    if ((c & 31) == 0) { a1[c >> 5] = s1; a2[c >> 5] = s2; }
    __syncthreads();
    s1 = 0.f; s2 = 0.f;
#pragma unroll
    for (int i = 0; i < 16; i++) { s1 += a1[i]; s2 += a2[i]; }
    float mean = s1 / (float)DM;
    float var = s2 / (float)DM - mean * mean;
    float r = rsqrtf(var + 1e-5f);
    float o = (v - mean) * r * w[c] + b[c];
    hn[idx] = o;
    store_split(oh, ol, idx, o);
}

// -------- fused attention reduce + bias + tanh + Wa2 dot -> score -----------
__global__ __launch_bounds__(128) void reduce_score_k(
    const float* __restrict__ part, int slices,
    const float* __restrict__ ba1, const float* __restrict__ Wa2,
    const float* __restrict__ ba2, float* __restrict__ s)
{
    int row = blockIdx.x, c = threadIdx.x;
    size_t idx = (size_t)row * 128 + c;
    float v = 0.f;
    for (int sl = 0; sl < slices; sl++) v += part[(size_t)sl * (L * 128) + idx];
    v = tanhf(v + ba1[c]);
    float acc = v * Wa2[c];
#pragma unroll
    for (int off = 16; off > 0; off >>= 1) acc += __shfl_xor_sync(0xffffffffu, acc, off);
    __shared__ float sm[4];
    if ((c & 31) == 0) sm[c >> 5] = acc;
    __syncthreads();
    if (c == 0) s[row] = sm[0] + sm[1] + sm[2] + sm[3] + ba2[0];
}

// --------------- depthwise conv + silu -> bf16 split only ------------------
__global__ __launch_bounds__(256) void conv_silu_k(const float* __restrict__ xz,
                                                   const float* __restrict__ cw,
                                                   const float* __restrict__ cb,
                                                   __nv_bfloat16* __restrict__ xih,
                                                   __nv_bfloat16* __restrict__ xil)
{
    int idx = blockIdx.x * 256 + threadIdx.x;
    int t = idx >> 10, d = idx & 1023;
    float w0 = cw[d * 4 + 0], w1 = cw[d * 4 + 1], w2 = cw[d * 4 + 2], w3 = cw[d * 4 + 3];
    float acc = cb[d];
    if (t >= 3) acc = fmaf(xz[(size_t)(t - 3) * 2048 + d], w0, acc);
    if (t >= 2) acc = fmaf(xz[(size_t)(t - 2) * 2048 + d], w1, acc);
    if (t >= 1) acc = fmaf(xz[(size_t)(t - 1) * 2048 + d], w2, acc);
    acc = fmaf(xz[(size_t)t * 2048 + d], w3, acc);
    store_split(xih, xil, idx, siluf(acc));
}

// ---------------------- chunked selective scan ------------------------------
__global__ __launch_bounds__(128) void scan_part_k(
    const float* __restrict__ delta,
    const __nv_bfloat16* __restrict__ xih, const __nv_bfloat16* __restrict__ xil,
    const float* __restrict__ dbc, const float* __restrict__ alog,
    float* __restrict__ aprod, float* __restrict__ hend)
{
    __shared__ float2 sdx[64][8];
    __shared__ float sB[64][16];
    int tid = threadIdx.x;
    int c = blockIdx.x;
    int d0 = blockIdx.y * 8;
    int dloc = tid >> 4, n = tid & 15;
    int d = d0 + dloc;
    float AdnL2 = -__expf(alog[d * DS + n]) * 1.4426950408889634f;
    float h = 0.f, ap = 1.f;
    int tbase = c * CHT;

    for (int sub = 0; sub < 2; sub++) {
        int t0 = tbase + sub * 64;
#pragma unroll
        for (int i = 0; i < 4; i++) {
            int e = tid + i * 128; int r = e >> 3, cc = e & 7;
            size_t gi = (size_t)(t0 + r) * DI + d0 + cc;
            float xv = __bfloat162float(xih[gi]) + __bfloat162float(xil[gi]);
            sdx[r][cc] = make_float2(delta[gi], xv);
        }
#pragma unroll
        for (int i = 0; i < 8; i++) {
            int e = tid + i * 128; int r = e >> 4, cc = e & 15;
            sB[r][cc] = dbc[(size_t)(t0 + r) * 64 + 32 + cc];
        }
        __syncthreads();
#pragma unroll 4
        for (int tt = 0; tt < 64; tt++) {
            float2 dx = sdx[tt][dloc];
            float a = ex2f(dx.x * AdnL2);
            h = fmaf(a, h, dx.x * dx.y * sB[tt][n]);
            ap *= a;
        }
        __syncthreads();
    }
    int idx = c * (DI * DS) + d * DS + n;
    aprod[idx] = ap;
    hend[idx] = h;
}

// phase 2+3 fused: inline carry recompute + local scan + output.
__global__ __launch_bounds__(128) void scan_fix_k(
    const float* __restrict__ delta,
    const __nv_bfloat16* __restrict__ xih, const __nv_bfloat16* __restrict__ xil,
    const float* __restrict__ dbc, const float* __restrict__ xz,
    const float* __restrict__ alog, const float* __restrict__ Dp,
    const float* __restrict__ aprod, const float* __restrict__ hend,
    __nv_bfloat16* __restrict__ yh, __nv_bfloat16* __restrict__ yl)
{
    __shared__ float4 sdxz[64][8];
    __shared__ float sBC[64][32];
    __shared__ float sp[64][8][16];
    __shared__ float sDv[8];
    int tid = threadIdx.x;
    int c = blockIdx.x;
    int d0 = blockIdx.y * 8;
    int dloc = tid >> 4, n = tid & 15;
    int d = d0 + dloc;
    float AdnL2 = -__expf(alog[d * DS + n]) * 1.4426950408889634f;
    if (tid < 8) sDv[tid] = Dp[d0 + tid];

    float h = 0.f;
    int snidx = d * DS + n;
    for (int ch = 0; ch < c; ch++) {
        int ii = ch * (DI * DS) + snidx;
        h = fmaf(aprod[ii], h, hend[ii]);
    }
    int tbase = c * CHT;

    for (int sub = 0; sub < 2; sub++) {
        int t0 = tbase + sub * 64;
#pragma unroll
        for (int i = 0; i < 4; i++) {
            int e = tid + i * 128; int r = e >> 3, cc = e & 7;
            size_t gi = (size_t)(t0 + r) * DI + d0 + cc;
            float xv = __bfloat162float(xih[gi]) + __bfloat162float(xil[gi]);
            float zz = xz[(size_t)(t0 + r) * 2048 + DI + d0 + cc];
            sdxz[r][cc] = make_float4(delta[gi], xv, zz, 0.f);
        }
#pragma unroll
        for (int i = 0; i < 16; i++) {
            int e = tid + i * 128; int r = e >> 5, cc = e & 31;
            sBC[r][cc] = dbc[(size_t)(t0 + r) * 64 + 32 + cc];
        }
        __syncthreads();
#pragma unroll 4
        for (int tt = 0; tt < 64; tt++) {
            float2 dx = *(const float2*)&sdxz[tt][dloc];
            float a = ex2f(dx.x * AdnL2);
            h = fmaf(a, h, dx.x * dx.y * sBC[tt][n]);
            sp[tt][dloc][n] = h * sBC[tt][16 + n];
        }
        __syncthreads();
#pragma unroll
        for (int i = 0; i < 4; i++) {
            int e = tid + i * 128; int r = e >> 3, cc = e & 7;
            float s = 0.f;
#pragma unroll
            for (int nn = 0; nn < 16; nn++) s += sp[r][cc][nn];
            float4 dxz = sdxz[r][cc];
            float val = (s + dxz.y * sDv[cc]) * siluf(dxz.z);
            store_split(yh, yl, (size_t)(t0 + r) * DI + d0 + cc, val);
        }
        __syncthreads();
    }
}

// ------------- fused softmax + pooling partial (16 t-slices) ---------------
__global__ __launch_bounds__(512) void pool_soft_k(const float* __restrict__ sc,
                                                   const float* __restrict__ hn,
                                                   float* __restrict__ part)
{
    __shared__ float red[16];
    __shared__ float e[L];
    __shared__ float stat;
    int b = blockIdx.x, tid = threadIdx.x;
    float4 v = *(const float4*)(sc + tid * 4);
    float m = fmaxf(fmaxf(v.x, v.y), fmaxf(v.z, v.w));
#pragma unroll
    for (int off = 16; off > 0; off >>= 1) m = fmaxf(m, __shfl_xor_sync(0xffffffffu, m, off));
    if ((tid & 31) == 0) red[tid >> 5] = m;
    __syncthreads();
    if (tid == 0) {
        float x = red[0];
#pragma unroll
        for (int i = 1; i < 16; i++) x = fmaxf(x, red[i]);
        stat = x;
    }
    __syncthreads();
    float M = stat;
    float e0 = __expf(v.x - M), e1 = __expf(v.y - M);
    float e2 = __expf(v.z - M), e3 = __expf(v.w - M);
    e[tid * 4 + 0] = e0; e[tid * 4 + 1] = e1;
    e[tid * 4 + 2] = e2; e[tid * 4 + 3] = e3;
    float ss = (e0 + e1) + (e2 + e3);
#pragma unroll
    for (int off = 16; off > 0; off >>= 1) ss += __shfl_xor_sync(0xffffffffu, ss, off);
    __syncthreads();
    if ((tid & 31) == 0) red[tid >> 5] = ss;
    __syncthreads();
    if (tid == 0) {
        float x = 0.f;
#pragma unroll
        for (int i = 0; i < 16; i++) x += red[i];
        stat = x;
    }
    __syncthreads();
    float inv = 1.f / stat;
    int t0 = b * 128;
    float acc = 0.f;
#pragma unroll 8
    for (int t = 0; t < 128; t++)
        acc = fmaf(e[t0 + t], hn[(size_t)(t0 + t) * DM + tid], acc);
    part[b * DM + tid] = acc * inv;
}

__global__ __launch_bounds__(512) void pool_red_k(const float* __restrict__ part,
                                                  float* __restrict__ pooled)
{
    int c = threadIdx.x;
    float acc = 0.f;
#pragma unroll
    for (int s = 0; s < 16; s++) acc += part[s * DM + c];
    pooled[c] = acc;
}

// ---------------- ConvTranspose2d specialized kernels ----------------------
__global__ void convt1_k(const float* __restrict__ in, const float* __restrict__ w,
                         const float* __restrict__ b, float* __restrict__ out,
                         int Cin, int Cout)
{
    int gw = (blockIdx.x * 256 + threadIdx.x) >> 5;
    int lane = threadIdx.x & 31;
    if (gw >= Cout * 16) return;
    int co = gw >> 4;
    int tap = gw & 15;
    const float* ip = in + lane;
    const float* wp = w + (size_t)(lane * Cout + co) * 16 + tap;
    float acc = 0.f;
    int iters = Cin >> 5;
    for (int i = 0; i < iters; i++) {
        acc = fmaf(*ip, *wp, acc);
        ip += 32;
        wp += (size_t)32 * Cout * 16;
    }
#pragma unroll
    for (int off = 16; off > 0; off >>= 1) acc += __shfl_xor_sync(0xffffffffu, acc, off);
    if (lane == 0) out[gw] = fmaxf(acc + b[co], 0.f);
}

__global__ void convt2_k(const float* __restrict__ in, const float* __restrict__ w,
                         const float* __restrict__ b, float* __restrict__ out,
                         int Cin, int Cout)
{
    int gw = (blockIdx.x * 256 + threadIdx.x) >> 5;
    int lane = threadIdx.x & 31;
    if (gw >= Cout * 256) return;
    int co = gw >> 8;
    int r = gw & 255;
    int oy = r >> 4, ox = r & 15;
    int ky = oy & 3, iy = oy >> 2;
    int kx = ox & 3, ix = ox >> 2;
    const float* ip = in + (size_t)lane * 16 + iy * 4 + ix;
    const float* wp = w + (size_t)(lane * Cout + co) * 16 + ky * 4 + kx;
    float acc = 0.f;
    int iters = Cin >> 5;
    for (int i = 0; i < iters; i++) {
        acc = fmaf(*ip, *wp, acc);
        ip += 32 * 16;
        wp += (size_t)32 * Cout * 16;
    }
#pragma unroll
    for (int off = 16; off > 0; off >>= 1) acc += __shfl_xor_sync(0xffffffffu, acc, off);
    if (lane == 0) out[gw] = fmaxf(acc + b[co], 0.f);
}

__global__ void convt_s2_k(const float* __restrict__ in, const float* __restrict__ w,
                           const float* __restrict__ b, float* __restrict__ out,
                           int Cin, int Cout, int Hin, int Hout,
                           int do_relu, int total)
{
    int gw = (blockIdx.x * 256 + threadIdx.x) >> 5;
    int lane = threadIdx.x & 31;
    if (gw >= total) return;
    int hw = Hout * Hout;
    int co = gw / hw;
    int r = gw % hw;
    int oy = r / Hout, ox = r % Hout;
    int p = (oy + 1) & 1, q = (ox + 1) & 1;
    int iy0 = (oy + 1 - p) >> 1, ix0 = (ox + 1 - q) >> 1;
    int HH = Hin * Hin;
    int iters = Cin >> 5;
    float acc = 0.f;
#pragma unroll
    for (int j = 0; j < 2; j++) {
        int iy = iy0 - j;
        if (iy < 0 || iy >= Hin) continue;
        int ky = p + 2 * j;
#pragma unroll
        for (int k = 0; k < 2; k++) {
            int ix = ix0 - k;
            if (ix < 0 || ix >= Hin) continue;
            int kx = q + 2 * k;
            const float* ip = in + (size_t)lane * HH + iy * Hin + ix;
            const float* wp = w + (size_t)(lane * Cout + co) * 16 + ky * 4 + kx;
            for (int i = 0; i < iters; i++) {
                acc = fmaf(*ip, *wp, acc);
                ip += 32 * HH;
                wp += (size_t)32 * Cout * 16;
            }
        }
    }
#pragma unroll
    for (int off = 16; off > 0; off >>= 1) acc += __shfl_xor_sync(0xffffffffu, acc, off);
    if (lane == 0) {
        float v = acc + b[co];
        out[gw] = do_relu ? fmaxf(v, 0.f) : v;
    }
}

// ------------------------------- launcher ----------------------------------
extern "C" void kernel_launch(void* const* d_in, const int* in_sizes, int n_in,
                              void* d_out, int out_size)
{
    const float* x       = (const float*)d_in[0];
    const float* coords  = (const float*)d_in[1];
    const float* W_fc1   = (const float*)d_in[2];
    const float* b_fc1   = (const float*)d_in[3];
    const float* W_pos   = (const float*)d_in[4];
    const float* b_pos   = (const float*)d_in[5];
    const float* in_w    = (const float*)d_in[6];
    const float* conv_w  = (const float*)d_in[7];
    const float* conv_b  = (const float*)d_in[8];
    const float* x_w     = (const float*)d_in[9];
    const float* dt_w    = (const float*)d_in[10];
    const float* dt_b    = (const float*)d_in[11];
    const float* A_log   = (const float*)d_in[12];
    const float* Dp      = (const float*)d_in[13];
    const float* out_w   = (const float*)d_in[14];
    const float* rms_w   = (const float*)d_in[15];
    const float* ln_w    = (const float*)d_in[16];
    const float* ln_b    = (const float*)d_in[17];
    const float* Wa1     = (const float*)d_in[18];
    const float* ba1     = (const float*)d_in[19];
    const float* Wa2     = (const float*)d_in[20];
    const float* ba2     = (const float*)d_in[21];
    const float* ct1_w   = (const float*)d_in[22];
    const float* ct1_b   = (const float*)d_in[23];
    const float* ct2_w   = (const float*)d_in[24];
    const float* ct2_b   = (const float*)d_in[25];
    const float* ct3_w   = (const float*)d_in[26];
    const float* ct3_b   = (const float*)d_in[27];
    const float* ct4_w   = (const float*)d_in[28];
    const float* ct4_b   = (const float*)d_in[29];
    const float* ct5_w   = (const float*)d_in[30];
    const float* ct5_b   = (const float*)d_in[31];

    float *h, *hn, *xz, *dbc, *delta, *sc, *pooled, *part;
    float *c1, *c2, *c3, *c4, *ap, *he;
    __nv_bfloat16 *xh, *xl, *hnh, *hnl, *yh, *yl, *xih, *xil, *dth, *dtl;
    __nv_bfloat16 *wfc1h, *wfc1l, *winh, *winl, *wouth, *woutl, *wa1h, *wa1l;
    __nv_bfloat16 *wxwh, *wxwl, *wdth, *wdtl;
    cudaGetSymbolAddress((void**)&h, g_h);
    cudaGetSymbolAddress((void**)&hn, g_hn);
    cudaGetSymbolAddress((void**)&xz, g_xz);
    cudaGetSymbolAddress((void**)&dbc, g_dbc);
    cudaGetSymbolAddress((void**)&delta, g_delta);
    cudaGetSymbolAddress((void**)&sc, g_s);
    cudaGetSymbolAddress((void**)&pooled, g_pooled);
    cudaGetSymbolAddress((void**)&part, g_part);
    cudaGetSymbolAddress((void**)&c1, g_c1);
    cudaGetSymbolAddress((void**)&c2, g_c2);
    cudaGetSymbolAddress((void**)&c3, g_c3);
    cudaGetSymbolAddress((void**)&c4, g_c4);
    cudaGetSymbolAddress((void**)&ap, g_ap);
    cudaGetSymbolAddress((void**)&he, g_he);
    cudaGetSymbolAddress((void**)&xh, g_xh);
    cudaGetSymbolAddress((void**)&xl, g_xl);
    cudaGetSymbolAddress((void**)&hnh, g_hnh);
    cudaGetSymbolAddress((void**)&hnl, g_hnl);
    cudaGetSymbolAddress((void**)&yh, g_yh);
    cudaGetSymbolAddress((void**)&yl, g_yl);
    cudaGetSymbolAddress((void**)&xih, g_xih);
    cudaGetSymbolAddress((void**)&xil, g_xil);
    cudaGetSymbolAddress((void**)&dth, g_dth);
    cudaGetSymbolAddress((void**)&dtl, g_dtl);
    cudaGetSymbolAddress((void**)&wfc1h, g_wfc1h);
    cudaGetSymbolAddress((void**)&wfc1l, g_wfc1l);
    cudaGetSymbolAddress((void**)&winh, g_winh);
    cudaGetSymbolAddress((void**)&winl, g_winl);
    cudaGetSymbolAddress((void**)&wouth, g_wouth);
    cudaGetSymbolAddress((void**)&woutl, g_woutl);
    cudaGetSymbolAddress((void**)&wa1h, g_wa1h);
    cudaGetSymbolAddress((void**)&wa1l, g_wa1l);
    cudaGetSymbolAddress((void**)&wxwh, g_wxwh);
    cudaGetSymbolAddress((void**)&wxwl, g_wxwl);
    cudaGetSymbolAddress((void**)&wdth, g_wdth);
    cudaGetSymbolAddress((void**)&wdtl, g_wdtl);

    cudaFuncSetAttribute(hmma_gemm_k, cudaFuncAttributeMaxDynamicSharedMemorySize, HSMEM);

    // prep (weights + x split in one kernel)
    wsplit_all_k<<<3840 + (L * 1024) / 256, 256>>>(
        W_fc1, in_w, out_w, Wa1, x_w, dt_w, x,
        wfc1h, wfc1l, winh, winl, wouth, woutl,
        wa1h, wa1l, wxwh, wxwl, wdth, wdtl, xh, xl);
    {
        dim3 g(8, 16, 2);
        hmma_gemm_k<<<g, 256, HSMEM>>>(L, DM, 1024, xh, xl, wfc1h, wfc1l, part, DM,
                                       0, nullptr);
        reduce_rms_k<<<L, 512>>>(part, 2, 1, b_fc1, coords, W_pos, b_pos,
                                 rms_w, h, hnh, hnl);
    }

    // ---- mamba layers ----
    for (int l = 0; l < 2; l++) {
        const float* cw  = conv_w + (size_t)l * DI * 4;
        const float* cb  = conv_b + (size_t)l * DI;
        const float* dtb = dt_b  + (size_t)l * DI;
        const float* al  = A_log + (size_t)l * DI * DS;
        const float* Dl  = Dp    + (size_t)l * DI;

        { // xz = hn @ in_w
            dim3 g(32, 16, 1);
            hmma_gemm_k<<<g, 256, HSMEM>>>(L, 2 * DI, DM, hnh, hnl,
                                           winh + (size_t)l * 2048 * 512,
                                           winl + (size_t)l * 2048 * 512,
                                           xz, 2 * DI, 0, nullptr);
        }

        conv_silu_k<<<(L * DI) / 256, 256>>>(xz, cw, cb, xih, xil);

        { // dbc = xi @ xw via HMMA (split-K 4) + reduce/split
            dim3 g(1, 16, 4);
            hmma_gemm_k<<<g, 256, HSMEM>>>(L, 64, DI, xih, xil,
                                           wxwh + (size_t)l * 64 * 1024,
                                           wxwl + (size_t)l * 64 * 1024,
                                           part, 64, 0, nullptr);
            reduce_dbc_k<<<(L * 64 + 255) / 256, 256>>>(part, 4, dbc, dth, dtl);
        }

        { // delta = softplus(dt @ dtw + dtb) via HMMA (K=32, NC=1)
            dim3 g(16, 16, 1);
            hmma_gemm_k<<<g, 256, HSMEM>>>(L, DI, DTR, dth, dtl,
                                           wdth + (size_t)l * 1024 * 32,
                                           wdtl + (size_t)l * 1024 * 32,
                                           delta, DI, 3, dtb);
        }

        // chunked parallel scan (carry fused into fix)
        scan_part_k<<<dim3(NCH, DI / 8), 128>>>(delta, xih, xil, dbc, al, ap, he);
        scan_fix_k<<<dim3(NCH, DI / 8), 128>>>(delta, xih, xil, dbc, xz, al, Dl,
                                               ap, he, yh, yl);

        { // h += y @ out_w (split-K 2) + fused norm
            dim3 g(8, 16, 2);
            hmma_gemm_k<<<g, 256, HSMEM>>>(L, DM, DI, yh, yl,
                                           wouth + (size_t)l * 512 * 1024,
                                           woutl + (size_t)l * 512 * 1024,
                                           part, DM, 0, nullptr);
            if (l == 0) {
                reduce_rms_k<<<L, 512>>>(part, 2, 2, nullptr, nullptr, nullptr,
                                         nullptr, rms_w + DM, h, hnh, hnl);
            } else {
                reduce_ln_k<<<L, 512>>>(part, 2, h, ln_w, ln_b, hn, hnh, hnl);
            }
        }
    }

    // ---- attention: fused reduce+tanh+score, fused softmax+pool ----
    {
        dim3 g(2, 16, 4);
        hmma_gemm_k<<<g, 256, HSMEM>>>(L, 128, DM, hnh, hnl, wa1h, wa1l, part, 128,
                                       0, nullptr);
        reduce_score_k<<<L, 128>>>(part, 4, ba1, Wa2, ba2, sc);
    }
    pool_soft_k<<<16, 512>>>(sc, hn, part);
    pool_red_k<<<1, 512>>>(part, pooled);

    // ---- ConvTranspose2d stack (specialized) ----
    convt1_k<<<(4096 * 32 + 255) / 256, 256>>>(pooled, ct1_w, ct1_b, c1, 512, 256);
    convt2_k<<<(32768 * 32 + 255) / 256, 256>>>(c1, ct2_w, ct2_b, c2, 256, 128);
    convt_s2_k<<<(65536 * 32 + 255) / 256, 256>>>(c2, ct3_w, ct3_b, c3,
                                                  128, 64, 16, 32, 1, 65536);
    convt_s2_k<<<(131072 * 32 + 255) / 256, 256>>>(c3, ct4_w, ct4_b, c4,
                                                   64, 32, 32, 64, 1, 131072);
    convt_s2_k<<<(180224 * 32 + 255) / 256, 256>>>(c4, ct5_w, ct5_b, (float*)d_out,
                                                   32, 11, 64, 128, 0, 180224);
}